// round 15
// baseline (speedup 1.0000x reference)
#include <cuda_runtime.h>
#include <math.h>

#define NB 16
#define NH 16
#define LFR 256
#define L 245760
#define NT 15360          // level-0 tiles (16 samples) per row
#define NJ 960            // level-1 tiles (256 samples) per row
#define TWOPI_F 6.28318530717958647692f
#define RINV ((float)(1.0 / 48000.0))   // fl32(1/48000)
#define CW_A 6.28125f
#define CW_B 1.9353071795864769e-3f
#define MAGIC 12582912.0f               // 1.5*2^23

typedef unsigned long long u64;

__device__ float g_A[NB * NH * LFR];    // exp(amps)
__device__ float g_P1[NB * NT * NH];    // inclusive level-1 prefixes, [n][q][h]
__device__ float g_S1[NB * NH * NJ];    // level-1 sums, [row][j]
__device__ float g_E2t[NB * NJ * NH];   // exclusive level-2 prefixes, [n][j][h]

static __device__ __forceinline__ float fadd(float a, float b) { return __fadd_rn(a, b); }
static __device__ __forceinline__ float fmul(float a, float b) { return __fmul_rn(a, b); }

// ---- f32x2 packed helpers (osc only; never in scan) ----
static __device__ __forceinline__ u64 pk(float lo, float hi) {
    u64 r; asm("mov.b64 %0,{%1,%2};" : "=l"(r) : "f"(lo), "f"(hi)); return r;
}
static __device__ __forceinline__ void upk(u64 v, float& lo, float& hi) {
    asm("mov.b64 {%0,%1},%2;" : "=f"(lo), "=f"(hi) : "l"(v));
}
static __device__ __forceinline__ u64 f2add(u64 a, u64 b) {
    u64 r; asm("add.rn.f32x2 %0,%1,%2;" : "=l"(r) : "l"(a), "l"(b)); return r;
}
static __device__ __forceinline__ u64 f2mul(u64 a, u64 b) {
    u64 r; asm("mul.rn.f32x2 %0,%1,%2;" : "=l"(r) : "l"(a), "l"(b)); return r;
}
static __device__ __forceinline__ u64 f2fma(u64 a, u64 b, u64 c) {
    u64 r; asm("fma.rn.f32x2 %0,%1,%2,%3;" : "=l"(r) : "l"(a), "l"(b), "l"(c)); return r;
}

// reference leaf: fl( fl(f0up * h) * fl(1/48000) )
static __device__ __forceinline__ float leaf(float f0up, float mh) {
    return __fmul_rn(__fmul_rn(f0up, mh), RINV);
}

// reference-exact interp coords for sample t (mul-then-sub, no fma)
static __device__ __forceinline__ void coords(int t, int& i0, int& i1,
                                              float& w, float& omw) {
    const float C960 = (float)(1.0 / 960.0);
    float a = __fadd_rn((float)t, 0.5f);
    float pos = __fsub_rn(__fmul_rn(a, C960), 0.5f);
    pos = fminf(fmaxf(pos, 0.0f), 255.0f);
    i0 = (int)pos;
    i1 = min(i0 + 1, LFR - 1);
    w = __fsub_rn(pos, (float)i0);
    omw = __fsub_rn(1.0f, w);
}

// ---------------------------------------------------------------------------
// scan1: scalar scan + fused exp(amps); fold loop now reads smem via float4
// (same values, same fold order — bit-identical).
// ---------------------------------------------------------------------------
__global__ void __launch_bounds__(256) scan1_kernel(const float* __restrict__ f0raw,
                                                    const float* __restrict__ amps) {
    __shared__ float sf0[LFR];
    __shared__ float smf[4096];
    int n = blockIdx.y;
    int tid = threadIdx.x;
    int baset = blockIdx.x * 4096;

    {
        int bid = blockIdx.y * 60 + blockIdx.x;
        int i = bid * 256 + tid;
        if (bid < 256) g_A[i] = expf(amps[i]);
    }

    if (tid < LFR) sf0[tid] = fmaxf(f0raw[n * LFR + tid], 20.0f);
    __syncthreads();
    for (int i = tid; i < 4096; i += 256) {
        int t = baset + i;
        int i0, i1; float w, omw;
        coords(t, i0, i1, w, omw);
        smf[i] = fadd(fmul(sf0[i0], omw), fmul(sf0[i1], w));
    }
    __syncthreads();

    int jl = tid >> 4;
    int h = tid & 15;
    int jg = blockIdx.x * 16 + jl;
    float mh = (float)(h + 1);
    const float4* b4 = (const float4*)(smf + jl * 256);
    float acc1 = 0.0f;
#pragma unroll
    for (int ss = 0; ss < 16; ss++) {
        float a = 0.0f;
#pragma unroll
        for (int s4 = 0; s4 < 4; s4++) {
            float4 v = b4[ss * 4 + s4];
            a = fadd(a, leaf(v.x, mh));
            a = fadd(a, leaf(v.y, mh));
            a = fadd(a, leaf(v.z, mh));
            a = fadd(a, leaf(v.w, mh));
        }
        acc1 = fadd(acc1, a);
        g_P1[((n * NT + jg * 16 + ss) << 4) + h] = acc1;
    }
    g_S1[(n * 16 + h) * NJ + jg] = acc1;
}

// ---------------------------------------------------------------------------
// scan2: VERBATIM (scalar).
// ---------------------------------------------------------------------------
__global__ void __launch_bounds__(960) scan2_kernel() {
    __shared__ float s1[960];
    __shared__ float in2[960];
    __shared__ float r2s[960];
    __shared__ float s2[60];
    __shared__ float in3[64];
    __shared__ float s3[4];
    __shared__ float r4[4];
    __shared__ float r3[64];
    int row = blockIdx.x;
    int n = row >> 4, h = row & 15;
    int tid = threadIdx.x;

    s1[tid] = g_S1[row * NJ + tid];
    __syncthreads();

    if (tid < 60) {
        float a = 0.0f;
#pragma unroll
        for (int s = 0; s < 16; s++) { a = fadd(a, s1[tid * 16 + s]); in2[tid * 16 + s] = a; }
        s2[tid] = a;
    }
    __syncthreads();
    if (tid < 4) {
        float a = 0.0f;
#pragma unroll
        for (int s = 0; s < 16; s++) {
            int i = tid * 16 + s;
            float v = (i < 60) ? s2[i] : 0.0f;
            a = fadd(a, v);
            in3[i] = a;
        }
        s3[tid] = a;
    }
    __syncthreads();
    if (tid == 0) {
        float a = 0.0f;
#pragma unroll
        for (int p = 0; p < 4; p++) { a = fadd(a, s3[p]); r4[p] = a; }
    }
    __syncthreads();
    if (tid < 64)
        r3[tid] = (tid < 16) ? in3[tid] : fadd(in3[tid], r4[(tid >> 4) - 1]);
    __syncthreads();
    r2s[tid] = (tid < 16) ? in2[tid] : fadd(in2[tid], r3[(tid >> 4) - 1]);
    __syncthreads();

    float E2 = (tid == 0) ? 0.0f : r2s[tid - 1];
    g_E2t[((n * NJ + tid) << 4) + h] = E2;
}

// ---------------------------------------------------------------------------
// Oscillator: 2 threads/tile, 8 harmonics each (4 f32x2 pairs). Per-block
// smem pre-pass computes w[1024] and f0u[1024] once (bit-identical formulas);
// inner loop replaces the 11-op prelude with 2 broadcast LDS.
// ---------------------------------------------------------------------------
__global__ void __launch_bounds__(128) osc_kernel(const float* __restrict__ f0raw,
                                                  float* __restrict__ out) {
    __shared__ float sA[NH * LFR];
    __shared__ float sf0[LFR];
    __shared__ float sw[1024];
    __shared__ float sfu[1024];
    __shared__ float stage[64 * 17];
    int n = blockIdx.y;
    int tid = threadIdx.x;
    {
        const float4* src = (const float4*)(g_A + n * NH * LFR);
        float4* dst = (float4*)sA;
        for (int i = tid; i < NH * LFR / 4; i += 128) dst[i] = src[i];
    }
    for (int i = tid; i < LFR; i += 128) sf0[i] = fmaxf(f0raw[n * LFR + i], 20.0f);
    __syncthreads();

    // pre-pass: per-sample w and f0u (bit-identical to previous inner-loop calc)
    for (int i = tid; i < 1024; i += 128) {
        int t = blockIdx.x * 1024 + i;
        int i0, i1; float w, omw;
        coords(t, i0, i1, w, omw);
        sw[i] = w;
        sfu[i] = fadd(fmul(sf0[i0], omw), fmul(sf0[i1], w));
    }
    __syncthreads();

    int ql = tid >> 1;          // tile within block (0..63)
    int hq = tid & 1;           // harmonic half (h = 8*hq .. 8*hq+7)
    int q = blockIdx.x * 64 + ql;
    int t0 = q * 16;

    int i0, i1; float w0, omw0;
    coords(t0, i0, i1, w0, omw0);
    float v0 = sf0[i0], v1 = sf0[i1];
    (void)v0; (void)v1;

    u64 Ev2[4], run2[4], a02[4], da2[4], mh2[4];
    if (q == 0) {
#pragma unroll
        for (int p = 0; p < 4; p++) Ev2[p] = pk(0.0f, 0.0f);
    } else {
        const float* p1b = &g_P1[((n * NT + q - 1) << 4) + hq * 8];
        const float* e2b = &g_E2t[((n * NJ + ((q - 1) >> 4)) << 4) + hq * 8];
        float4 p1a = *(const float4*)p1b,       p1c = *(const float4*)(p1b + 4);
        float4 e2a = *(const float4*)e2b,       e2c = *(const float4*)(e2b + 4);
        Ev2[0] = pk(fadd(p1a.x, e2a.x), fadd(p1a.y, e2a.y));
        Ev2[1] = pk(fadd(p1a.z, e2a.z), fadd(p1a.w, e2a.w));
        Ev2[2] = pk(fadd(p1c.x, e2c.x), fadd(p1c.y, e2c.y));
        Ev2[3] = pk(fadd(p1c.z, e2c.z), fadd(p1c.w, e2c.w));
    }
#pragma unroll
    for (int p = 0; p < 4; p++) {
        int h = hq * 8 + p * 2;
        float a0l = sA[h * LFR + i0],       a0h = sA[(h + 1) * LFR + i0];
        float a1l = sA[h * LFR + i1],       a1h = sA[(h + 1) * LFR + i1];
        a02[p] = pk(a0l, a0h);
        da2[p] = pk(a1l - a0l, a1h - a0h);
        run2[p] = pk(0.0f, 0.0f);
        mh2[p] = pk((float)(h + 1), (float)(h + 2));
    }
    const u64 K2   = pk(RINV, RINV);
    const u64 TP2  = pk(TWOPI_F, TWOPI_F);
    const u64 MG2  = pk(MAGIC, MAGIC);
    const u64 NMG2 = pk(-MAGIC, -MAGIC);
    const u64 NCA2 = pk(-CW_A, -CW_A);
    const u64 NCB2 = pk(-CW_B, -CW_B);

#pragma unroll
    for (int s = 0; s < 16; s++) {
        float w = sw[ql * 16 + s];
        float f0u = sfu[ql * 16 + s];
        u64 f0u2 = pk(f0u, f0u);
        u64 w2 = pk(w, w);
        u64 acc2 = pk(0.0f, 0.0f);
#pragma unroll
        for (int p = 0; p < 4; p++) {
            u64 lv = f2mul(f2mul(f0u2, mh2[p]), K2);   // fl(fl(f0u*h)*R) per comp
            run2[p] = f2add(run2[p], lv);
            u64 dt = f2add(run2[p], Ev2[p]);
            u64 th = f2mul(TP2, dt);
            u64 k = f2add(f2add(dt, MG2), NMG2);        // rintf(dt) per comp (RNE)
            u64 r = f2fma(k, NCA2, th);
            r = f2fma(k, NCB2, r);
            float rl, rh; upk(r, rl, rh);
            float sl = __sinf(rl);
            float sh = __sinf(rh);
            u64 amp = f2fma(w2, da2[p], a02[p]);
            acc2 = f2fma(pk(sl, sh), amp, acc2);
        }
        float al, ah; upk(acc2, al, ah);
        float part = fadd(al, ah);
        part = fadd(part, __shfl_xor_sync(0xffffffffu, part, 1));
        if (hq == 0) stage[ql * 17 + s] = __fmul_rn(part, 0.0625f);
    }
    __syncthreads();

    float* obase = out + n * L + blockIdx.x * 1024;
    for (int i = tid; i < 1024; i += 128)
        obase[i] = stage[(i >> 4) * 17 + (i & 15)];
}

// ---------------------------------------------------------------------------
extern "C" void kernel_launch(void* const* d_in, const int* in_sizes, int n_in,
                              void* d_out, int out_size) {
    const float* amps = (const float*)d_in[0];
    const float* f0 = (const float*)d_in[1];
    if (n_in >= 2 && in_sizes[0] == NB * LFR && in_sizes[1] == NB * NH * LFR) {
        const float* tmp = amps; amps = f0; f0 = tmp;
    }
    float* out = (float*)d_out;

    scan1_kernel<<<dim3(NJ / 16, NB), 256>>>(f0, amps);
    scan2_kernel<<<NB * NH, 960>>>();
    osc_kernel<<<dim3(NT / 64, NB), 128>>>(f0, out);
}

// round 16
// speedup vs baseline: 1.0029x; 1.0029x over previous
#include <cuda_runtime.h>
#include <math.h>

#define NB 16
#define NH 16
#define LFR 256
#define L 245760
#define NT 15360          // level-0 tiles (16 samples) per row
#define NJ 960            // level-1 tiles (256 samples) per row
#define TWOPI_F 6.28318530717958647692f
#define RINV ((float)(1.0 / 48000.0))   // fl32(1/48000)
#define CW_A 6.28125f
#define CW_B 1.9353071795864769e-3f
#define MAGIC 12582912.0f               // 1.5*2^23

typedef unsigned long long u64;

__device__ float g_A[NB * NH * LFR];    // exp(amps)
__device__ float g_P1[NB * NT * NH];    // inclusive level-1 prefixes, [n][q][h]
__device__ float g_S1[NB * NH * NJ];    // level-1 sums, [row][j]
__device__ float g_E2t[NB * NJ * NH];   // exclusive level-2 prefixes, [n][j][h]

static __device__ __forceinline__ float fadd(float a, float b) { return __fadd_rn(a, b); }
static __device__ __forceinline__ float fmul(float a, float b) { return __fmul_rn(a, b); }

// ---- f32x2 packed helpers (osc only; never in scan) ----
static __device__ __forceinline__ u64 pk(float lo, float hi) {
    u64 r; asm("mov.b64 %0,{%1,%2};" : "=l"(r) : "f"(lo), "f"(hi)); return r;
}
static __device__ __forceinline__ void upk(u64 v, float& lo, float& hi) {
    asm("mov.b64 {%0,%1},%2;" : "=f"(lo), "=f"(hi) : "l"(v));
}
static __device__ __forceinline__ u64 f2add(u64 a, u64 b) {
    u64 r; asm("add.rn.f32x2 %0,%1,%2;" : "=l"(r) : "l"(a), "l"(b)); return r;
}
static __device__ __forceinline__ u64 f2mul(u64 a, u64 b) {
    u64 r; asm("mul.rn.f32x2 %0,%1,%2;" : "=l"(r) : "l"(a), "l"(b)); return r;
}
static __device__ __forceinline__ u64 f2fma(u64 a, u64 b, u64 c) {
    u64 r; asm("fma.rn.f32x2 %0,%1,%2,%3;" : "=l"(r) : "l"(a), "l"(b), "l"(c)); return r;
}

// reference leaf: fl( fl(f0up * h) * fl(1/48000) )
static __device__ __forceinline__ float leaf(float f0up, float mh) {
    return __fmul_rn(__fmul_rn(f0up, mh), RINV);
}

// reference-exact interp coords for sample t (mul-then-sub, no fma)
static __device__ __forceinline__ void coords(int t, int& i0, int& i1,
                                              float& w, float& omw) {
    const float C960 = (float)(1.0 / 960.0);
    float a = __fadd_rn((float)t, 0.5f);
    float pos = __fsub_rn(__fmul_rn(a, C960), 0.5f);
    pos = fminf(fmaxf(pos, 0.0f), 255.0f);
    i0 = (int)pos;
    i1 = min(i0 + 1, LFR - 1);
    w = __fsub_rn(pos, (float)i0);
    omw = __fsub_rn(1.0f, w);
}

// ---------------------------------------------------------------------------
// scan1: 512 threads. Phase A: 2 threads per (tile,h) each compute 8 inner
// 16-leaf sums (identical fold order) into smem. Phase B: low half does the
// serial 16-add chain over the SAME a_ss values — bit-identical to R14.
// Fused exp(amps) distributed over first 128 blocks.
// ---------------------------------------------------------------------------
__global__ void __launch_bounds__(512) scan1_kernel(const float* __restrict__ f0raw,
                                                    const float* __restrict__ amps) {
    __shared__ float sf0[LFR];
    __shared__ float smf[4096];
    __shared__ float sa[4096];          // [ss][jl*16+h]
    int n = blockIdx.y;
    int tid = threadIdx.x;
    int baset = blockIdx.x * 4096;

    {
        int bid = blockIdx.y * 60 + blockIdx.x;
        int i = bid * 512 + tid;
        if (bid < 128) g_A[i] = expf(amps[i]);
    }

    if (tid < LFR) sf0[tid] = fmaxf(f0raw[n * LFR + tid], 20.0f);
    __syncthreads();
    for (int i = tid; i < 4096; i += 512) {
        int t = baset + i;
        int i0, i1; float w, omw;
        coords(t, i0, i1, w, omw);
        smf[i] = fadd(fmul(sf0[i0], omw), fmul(sf0[i1], w));
    }
    __syncthreads();

    int half = tid >> 8;
    int jl = (tid & 255) >> 4;
    int h = tid & 15;
    float mh = (float)(h + 1);
    const float4* b4 = (const float4*)(smf + jl * 256);
#pragma unroll
    for (int s8 = 0; s8 < 8; s8++) {
        int ss = half * 8 + s8;
        float a = 0.0f;
#pragma unroll
        for (int s4 = 0; s4 < 4; s4++) {
            float4 v = b4[ss * 4 + s4];
            a = fadd(a, leaf(v.x, mh));
            a = fadd(a, leaf(v.y, mh));
            a = fadd(a, leaf(v.z, mh));
            a = fadd(a, leaf(v.w, mh));
        }
        sa[ss * 256 + jl * 16 + h] = a;
    }
    __syncthreads();

    if (half == 0) {
        int jg = blockIdx.x * 16 + jl;
        float acc1 = 0.0f;
#pragma unroll
        for (int ss = 0; ss < 16; ss++) {
            acc1 = fadd(acc1, sa[ss * 256 + jl * 16 + h]);
            g_P1[((n * NT + jg * 16 + ss) << 4) + h] = acc1;
        }
        g_S1[(n * 16 + h) * NJ + jg] = acc1;
    }
}

// ---------------------------------------------------------------------------
// scan2: VERBATIM (scalar).
// ---------------------------------------------------------------------------
__global__ void __launch_bounds__(960) scan2_kernel() {
    __shared__ float s1[960];
    __shared__ float in2[960];
    __shared__ float r2s[960];
    __shared__ float s2[60];
    __shared__ float in3[64];
    __shared__ float s3[4];
    __shared__ float r4[4];
    __shared__ float r3[64];
    int row = blockIdx.x;
    int n = row >> 4, h = row & 15;
    int tid = threadIdx.x;

    s1[tid] = g_S1[row * NJ + tid];
    __syncthreads();

    if (tid < 60) {
        float a = 0.0f;
#pragma unroll
        for (int s = 0; s < 16; s++) { a = fadd(a, s1[tid * 16 + s]); in2[tid * 16 + s] = a; }
        s2[tid] = a;
    }
    __syncthreads();
    if (tid < 4) {
        float a = 0.0f;
#pragma unroll
        for (int s = 0; s < 16; s++) {
            int i = tid * 16 + s;
            float v = (i < 60) ? s2[i] : 0.0f;
            a = fadd(a, v);
            in3[i] = a;
        }
        s3[tid] = a;
    }
    __syncthreads();
    if (tid == 0) {
        float a = 0.0f;
#pragma unroll
        for (int p = 0; p < 4; p++) { a = fadd(a, s3[p]); r4[p] = a; }
    }
    __syncthreads();
    if (tid < 64)
        r3[tid] = (tid < 16) ? in3[tid] : fadd(in3[tid], r4[(tid >> 4) - 1]);
    __syncthreads();
    r2s[tid] = (tid < 16) ? in2[tid] : fadd(in2[tid], r3[(tid >> 4) - 1]);
    __syncthreads();

    float E2 = (tid == 0) ? 0.0f : r2s[tid - 1];
    g_E2t[((n * NJ + tid) << 4) + h] = E2;
}

// ---------------------------------------------------------------------------
// Oscillator: VERBATIM R14 (2 threads/tile, 8 harmonics each, no pre-pass).
// ---------------------------------------------------------------------------
__global__ void __launch_bounds__(128) osc_kernel(const float* __restrict__ f0raw,
                                                  float* __restrict__ out) {
    __shared__ float sA[NH * LFR];
    __shared__ float sf0[LFR];
    __shared__ float stage[64 * 17];
    int n = blockIdx.y;
    int tid = threadIdx.x;
    {
        const float4* src = (const float4*)(g_A + n * NH * LFR);
        float4* dst = (float4*)sA;
        for (int i = tid; i < NH * LFR / 4; i += 128) dst[i] = src[i];
    }
    for (int i = tid; i < LFR; i += 128) sf0[i] = fmaxf(f0raw[n * LFR + i], 20.0f);
    __syncthreads();

    int ql = tid >> 1;          // tile within block (0..63)
    int hq = tid & 1;           // harmonic half (h = 8*hq .. 8*hq+7)
    int q = blockIdx.x * 64 + ql;
    int t0 = q * 16;

    int i0, i1; float w0, omw0;
    coords(t0, i0, i1, w0, omw0);
    float i0f = (float)i0;
    float v0 = sf0[i0], v1 = sf0[i1];

    u64 Ev2[4], run2[4], a02[4], da2[4], mh2[4];
    if (q == 0) {
#pragma unroll
        for (int p = 0; p < 4; p++) Ev2[p] = pk(0.0f, 0.0f);
    } else {
        const float* p1b = &g_P1[((n * NT + q - 1) << 4) + hq * 8];
        const float* e2b = &g_E2t[((n * NJ + ((q - 1) >> 4)) << 4) + hq * 8];
        float4 p1a = *(const float4*)p1b,       p1c = *(const float4*)(p1b + 4);
        float4 e2a = *(const float4*)e2b,       e2c = *(const float4*)(e2b + 4);
        Ev2[0] = pk(fadd(p1a.x, e2a.x), fadd(p1a.y, e2a.y));
        Ev2[1] = pk(fadd(p1a.z, e2a.z), fadd(p1a.w, e2a.w));
        Ev2[2] = pk(fadd(p1c.x, e2c.x), fadd(p1c.y, e2c.y));
        Ev2[3] = pk(fadd(p1c.z, e2c.z), fadd(p1c.w, e2c.w));
    }
#pragma unroll
    for (int p = 0; p < 4; p++) {
        int h = hq * 8 + p * 2;
        float a0l = sA[h * LFR + i0],       a0h = sA[(h + 1) * LFR + i0];
        float a1l = sA[h * LFR + i1],       a1h = sA[(h + 1) * LFR + i1];
        a02[p] = pk(a0l, a0h);
        da2[p] = pk(a1l - a0l, a1h - a0h);
        run2[p] = pk(0.0f, 0.0f);
        mh2[p] = pk((float)(h + 1), (float)(h + 2));
    }
    const u64 K2   = pk(RINV, RINV);
    const u64 TP2  = pk(TWOPI_F, TWOPI_F);
    const u64 MG2  = pk(MAGIC, MAGIC);
    const u64 NMG2 = pk(-MAGIC, -MAGIC);
    const u64 NCA2 = pk(-CW_A, -CW_A);
    const u64 NCB2 = pk(-CW_B, -CW_B);
    const float C960 = (float)(1.0 / 960.0);

#pragma unroll
    for (int s = 0; s < 16; s++) {
        int t = t0 + s;
        float a = __fadd_rn((float)t, 0.5f);
        float pos = __fsub_rn(__fmul_rn(a, C960), 0.5f);
        pos = fminf(fmaxf(pos, 0.0f), 255.0f);
        float w = __fsub_rn(pos, i0f);
        float f0u = fadd(fmul(v0, __fsub_rn(1.0f, w)), fmul(v1, w));
        u64 f0u2 = pk(f0u, f0u);
        u64 w2 = pk(w, w);
        u64 acc2 = pk(0.0f, 0.0f);
#pragma unroll
        for (int p = 0; p < 4; p++) {
            u64 lv = f2mul(f2mul(f0u2, mh2[p]), K2);   // fl(fl(f0u*h)*R) per comp
            run2[p] = f2add(run2[p], lv);
            u64 dt = f2add(run2[p], Ev2[p]);
            u64 th = f2mul(TP2, dt);
            u64 k = f2add(f2add(dt, MG2), NMG2);        // rintf(dt) per comp (RNE)
            u64 r = f2fma(k, NCA2, th);
            r = f2fma(k, NCB2, r);
            float rl, rh; upk(r, rl, rh);
            float sl = __sinf(rl);
            float sh = __sinf(rh);
            u64 amp = f2fma(w2, da2[p], a02[p]);
            acc2 = f2fma(pk(sl, sh), amp, acc2);
        }
        float al, ah; upk(acc2, al, ah);
        float part = fadd(al, ah);
        part = fadd(part, __shfl_xor_sync(0xffffffffu, part, 1));
        if (hq == 0) stage[ql * 17 + s] = __fmul_rn(part, 0.0625f);
    }
    __syncthreads();

    float* obase = out + n * L + blockIdx.x * 1024;
    for (int i = tid; i < 1024; i += 128)
        obase[i] = stage[(i >> 4) * 17 + (i & 15)];
}

// ---------------------------------------------------------------------------
extern "C" void kernel_launch(void* const* d_in, const int* in_sizes, int n_in,
                              void* d_out, int out_size) {
    const float* amps = (const float*)d_in[0];
    const float* f0 = (const float*)d_in[1];
    if (n_in >= 2 && in_sizes[0] == NB * LFR && in_sizes[1] == NB * NH * LFR) {
        const float* tmp = amps; amps = f0; f0 = tmp;
    }
    float* out = (float*)d_out;

    scan1_kernel<<<dim3(NJ / 16, NB), 512>>>(f0, amps);
    scan2_kernel<<<NB * NH, 960>>>();
    osc_kernel<<<dim3(NT / 64, NB), 128>>>(f0, out);
}